// round 17
// baseline (speedup 1.0000x reference)
#include <cuda_runtime.h>
#include <cuda_bf16.h>
#include <cstddef>

#define DK 64
#define TPB 160             // 5 warps
#define ITEM_BLOCKS 444
#define B_MAX 4096

// Scratch (no cudaMalloc allowed)
__device__ float g_G1[DK * DK];     // item_W^T item_W   (atomic)
__device__ float g_G2[DK * DK];     // u_emb^T u_emb     (atomic)
__device__ float g_posp[B_MAX];     // per-row pos-loss partials

// ---- packed f32x2 helpers (Blackwell FFMA2; full fp32 precision) ----------
__device__ __forceinline__ unsigned long long pack2(float x, float y) {
    unsigned long long r;
    asm("mov.b64 %0, {%1,%2};" : "=l"(r) : "f"(x), "f"(y));
    return r;
}
__device__ __forceinline__ unsigned long long fma2(unsigned long long a,
                                                   unsigned long long b,
                                                   unsigned long long c) {
    unsigned long long d;
    asm("fma.rn.f32x2 %0, %1, %2, %3;" : "=l"(d) : "l"(a), "l"(b), "l"(c));
    return d;
}
__device__ __forceinline__ float2 unpack2(unsigned long long v) {
    float2 r;
    asm("mov.b64 {%0,%1}, %2;" : "=f"(r.x), "=f"(r.y) : "l"(v));
    return r;
}

// Gram inner step: acc2[a][0] += {ai,ai}*{aj0,aj1}, acc2[a][1] += {ai,ai}*{aj2,aj3}
__device__ __forceinline__ void gram_step(unsigned long long acc2[4][2],
                                          float4 vi, float4 vj) {
    const unsigned long long aj01 = pack2(vj.x, vj.y);
    const unsigned long long aj23 = pack2(vj.z, vj.w);
    const float ai[4] = {vi.x, vi.y, vi.z, vi.w};
#pragma unroll
    for (int a = 0; a < 4; a++) {
        const unsigned long long aii = pack2(ai[a], ai[a]);
        acc2[a][0] = fma2(aii, aj01, acc2[a][0]);
        acc2[a][1] = fma2(aii, aj23, acc2[a][1]);
    }
}

// ---------------------------------------------------------------------------
// One kernel, three block roles:
//   [0, ITEM_BLOCKS)               : item Gram (upper-tri 4x4 tiles, 136 thr)
//   [ITEM_BLOCKS, ITEM_BLOCKS+nG2) : user Gram (64 gathered rows per block)
//   [ITEM_BLOCKS+nG2, ...+B)       : pos_data_loss, one block per batch row
__global__ void __launch_bounds__(TPB)
k_fused(const int* __restrict__ uids,
        const int* __restrict__ pos_iids,
        const float* __restrict__ userW,
        const float* __restrict__ itemW,
        const float* __restrict__ h,
        int B, int L, int PAD, int R, int nG2) {
    __shared__ float sm[64 * DK];       // 16 KB tile / wu scratch
    __shared__ float wsum[TPB / 32];
    const int tid = threadIdx.x;
    const int bid = blockIdx.x;

    if (bid < ITEM_BLOCKS + nG2) {
        // ------------------ Gram path (item or user) ------------------
        const bool isItem = bid < ITEM_BLOCKS;
        int ti = 0, tj = 0;
        const bool active = tid < 136;
        if (active) {                       // upper-tri tile map
            int k = tid, t = 0;
            while (k >= 16 - t) { k -= 16 - t; t++; }
            ti = t; tj = t + k;
        }
        unsigned long long acc2[4][2];
#pragma unroll
        for (int a = 0; a < 4; a++) { acc2[a][0] = 0ull; acc2[a][1] = 0ull; }

        if (isItem) {
            const int n_tiles = (R + 63) / 64;
            for (int t = bid; t < n_tiles; t += ITEM_BLOCKS) {
                const int row0  = t * 64;
                const int valid = min(64, R - row0);
                __syncthreads();
                const float4* src = (const float4*)(itemW + (size_t)row0 * DK);
                float4* dst = (float4*)sm;
                for (int i = tid; i < valid * (DK / 4); i += TPB) dst[i] = src[i];
                __syncthreads();
                if (active) {
                    if (valid == 64) {
#pragma unroll 4
                        for (int r = 0; r < 64; r++)
                            gram_step(acc2,
                                      *(const float4*)&sm[r * DK + ti * 4],
                                      *(const float4*)&sm[r * DK + tj * 4]);
                    } else {
                        for (int r = 0; r < valid; r++)
                            gram_step(acc2,
                                      *(const float4*)&sm[r * DK + ti * 4],
                                      *(const float4*)&sm[r * DK + tj * 4]);
                    }
                }
            }
        } else {
            const int base = (bid - ITEM_BLOCKS) * 64;
            for (int i = tid; i < 64 * DK; i += TPB) {
                int u = base + (i >> 6);
                sm[i] = (u < B) ? userW[(size_t)uids[u] * DK + (i & 63)] : 0.f;
            }
            __syncthreads();
            if (active) {
#pragma unroll 4
                for (int r = 0; r < 64; r++)
                    gram_step(acc2,
                              *(const float4*)&sm[r * DK + ti * 4],
                              *(const float4*)&sm[r * DK + tj * 4]);
            }
        }
        if (active) {
            float* G = isItem ? g_G1 : g_G2;
            float acc[4][4];
#pragma unroll
            for (int a = 0; a < 4; a++) {
                float2 lo = unpack2(acc2[a][0]);
                float2 hi = unpack2(acc2[a][1]);
                acc[a][0] = lo.x; acc[a][1] = lo.y;
                acc[a][2] = hi.x; acc[a][3] = hi.y;
            }
#pragma unroll
            for (int a = 0; a < 4; a++)
#pragma unroll
                for (int b = 0; b < 4; b++)
                    atomicAdd(&G[(ti * 4 + a) * DK + tj * 4 + b], acc[a][b]);
            if (ti != tj) {
#pragma unroll
                for (int a = 0; a < 4; a++)
#pragma unroll
                    for (int b = 0; b < 4; b++)
                        atomicAdd(&G[(tj * 4 + b) * DK + ti * 4 + a], acc[a][b]);
            }
        }
    } else {
        // ---------- hpq: one block per batch row b (2 items per group) ----------
        const int b    = bid - ITEM_BLOCKS - nG2;
        const int lane = tid & 31, w = tid >> 5;
        const int sub  = lane & 7, grp = lane >> 3;

        // wu = userW[uids[b]] * h, computed in-block
        if (tid < DK / 4) {
            float4 hu = ((const float4*)h)[tid];
            float4 uu = ((const float4*)(userW + (size_t)uids[b] * DK))[tid];
            float4 r;
            r.x = hu.x * uu.x; r.y = hu.y * uu.y;
            r.z = hu.z * uu.z; r.w = hu.w * uu.w;
            ((float4*)sm)[tid] = r;
        }
        __syncthreads();

        const float4 w0 = ((const float4*)sm)[sub];        // bytes [0,128)
        const float4 w1 = ((const float4*)sm)[sub + 8];    // bytes [128,256)
        const int* ids = pos_iids + (size_t)b * L;

        float loss = 0.f;
        const int per_step = (TPB / 32) * 8;               // 40 items/step
        const int nsteps = (L + per_step - 1) / per_step;  // 5 for L=200
        for (int s = 0; s < nsteps; s++) {
            const int l1 = s * per_step + w * 8 + grp * 2;
            const int l2 = l1 + 1;
            const int i1 = (l1 < L) ? ids[l1] : PAD;       // PAD row is valid mem
            const int i2 = (l2 < L) ? ids[l2] : PAD;
            const float4* r1 = (const float4*)(itemW + (size_t)i1 * DK);
            const float4* r2 = (const float4*)(itemW + (size_t)i2 * DK);
            float4 a0 = r1[sub], a1 = r1[sub + 8];          // 4 indep LDG.128
            float4 b0 = r2[sub], b1 = r2[sub + 8];
            float d1 = a0.x * w0.x + a0.y * w0.y + a0.z * w0.z + a0.w * w0.w
                     + a1.x * w1.x + a1.y * w1.y + a1.z * w1.z + a1.w * w1.w;
            float d2 = b0.x * w0.x + b0.y * w0.y + b0.z * w0.z + b0.w * w0.w
                     + b1.x * w1.x + b1.y * w1.y + b1.z * w1.z + b1.w * w1.w;
            d1 += __shfl_xor_sync(0xffffffffu, d1, 4);
            d2 += __shfl_xor_sync(0xffffffffu, d2, 4);
            d1 += __shfl_xor_sync(0xffffffffu, d1, 2);
            d2 += __shfl_xor_sync(0xffffffffu, d2, 2);
            d1 += __shfl_xor_sync(0xffffffffu, d1, 1);
            d2 += __shfl_xor_sync(0xffffffffu, d2, 1);
            if (sub == 0) {
                if (l1 < L && i1 != PAD) loss += 0.9f * d1 * d1 - 2.0f * d1;
                if (l2 < L && i2 != PAD) loss += 0.9f * d2 * d2 - 2.0f * d2;
            }
        }
#pragma unroll
        for (int off = 16; off; off >>= 1)
            loss += __shfl_xor_sync(0xffffffffu, loss, off);
        if (lane == 0) wsum[w] = loss;
        __syncthreads();
        if (tid == 0) {
            float s = 0.f;
#pragma unroll
            for (int k = 0; k < TPB / 32; k++) s += wsum[k];
            g_posp[b] = s;                                 // no atomic
        }
    }
}

// ---------------------------------------------------------------------------
// Final combine (float; 512 threads; full 4096-elem coverage).
__global__ void k_combine(const float* __restrict__ h, float* __restrict__ out,
                          int B) {
    __shared__ float red[512];
    const int tid = threadIdx.x;

    float a0 = 0.f, a1 = 0.f, a2 = 0.f, a3 = 0.f;
#pragma unroll
    for (int base = 0; base < DK * DK; base += 2048) {
        int e0 = base + tid;
        int e1 = e0 + 512;
        int e2 = e0 + 1024;
        int e3 = e0 + 1536;
        a0 += g_G1[e0] * g_G2[e0] * h[e0 >> 6] * h[e0 & 63];
        a1 += g_G1[e1] * g_G2[e1] * h[e1 >> 6] * h[e1 & 63];
        a2 += g_G1[e2] * g_G2[e2] * h[e2 >> 6] * h[e2 & 63];
        a3 += g_G1[e3] * g_G2[e3] * h[e3 >> 6] * h[e3 & 63];
    }
    float s = 0.1f * ((a0 + a1) + (a2 + a3));

    float b0 = 0.f, b1 = 0.f, b2 = 0.f, b3 = 0.f;
    for (int i = tid; i < B; i += 2048) {
        b0 += g_posp[i];
        if (i + 512  < B) b1 += g_posp[i + 512];
        if (i + 1024 < B) b2 += g_posp[i + 1024];
        if (i + 1536 < B) b3 += g_posp[i + 1536];
    }
    s += (b0 + b1) + (b2 + b3);

    red[tid] = s;
    __syncthreads();
    for (int k = 256; k >= 32; k >>= 1) {
        if (tid < k) red[tid] += red[tid + k];
        __syncthreads();
    }
    if (tid < 32) {
        float v = red[tid];
#pragma unroll
        for (int off = 16; off; off >>= 1)
            v += __shfl_xor_sync(0xffffffffu, v, off);
        if (tid == 0) out[0] = v;
    }
}

// ---------------------------------------------------------------------------
extern "C" void kernel_launch(void* const* d_in, const int* in_sizes, int n_in,
                              void* d_out, int out_size) {
    const int*   uids     = (const int*)d_in[0];
    const int*   pos_iids = (const int*)d_in[1];
    const float* user_W   = (const float*)d_in[2];
    const float* item_W   = (const float*)d_in[3];
    const float* h        = (const float*)d_in[4];
    float* out = (float*)d_out;

    const int B   = in_sizes[0];          // 4096
    const int L   = in_sizes[1] / B;      // 200
    const int R   = in_sizes[3] / DK;     // 100001 item rows
    const int PAD = R - 1;                // padding item id
    const int nG2 = (B + 63) / 64;        // user-gram blocks

    void *pG1 = nullptr, *pG2 = nullptr;
    cudaGetSymbolAddress(&pG1, g_G1);
    cudaGetSymbolAddress(&pG2, g_G2);
    cudaMemsetAsync(pG1, 0, DK * DK * sizeof(float));
    cudaMemsetAsync(pG2, 0, DK * DK * sizeof(float));

    k_fused<<<ITEM_BLOCKS + nG2 + B, TPB>>>(uids, pos_iids, user_W, item_W, h,
                                            B, L, PAD, R, nG2);
    k_combine<<<1, 512>>>(h, out, B);
}